// round 13
// baseline (speedup 1.0000x reference)
#include <cuda_runtime.h>
#include <cuda_bf16.h>

// Problem constants (fixed by the benchmark's setup_inputs)
#define DD 128
#define HH 512
#define WW 512
#define NVOX (DD * HH * WW)     // 33554432
#define RAD 3
#define PATCH 343               // 7*7*7
#define KP 131072               // max_peaks
#define CAP (1 << 18)           // peak buffer capacity (expected ~65k peaks)
#define NBMAX 65536             // bucket array size; actual max bucket ~50331
#define THRESH_F 0.997f

// ---------------- device scratch (static; no allocations) ----------------
__device__ int g_count;
__device__ int g_hist[NBMAX];
__device__ int g_start[NBMAX + 1];
__device__ int g_cursor[NBMAX];
__device__ unsigned g_peak_idx[CAP];
__device__ float g_peak_val[CAP];
__device__ unsigned g_sorted_idx[CAP];

// ---------------- kernels ----------------

// Zero counter, histogram, and the output buffer (d_out is poisoned 0xAA).
__global__ void k_init(float* out, int out_elems) {
    int t = blockIdx.x * blockDim.x + threadIdx.x;
    int stride = gridDim.x * blockDim.x;
    if (t == 0) g_count = 0;
    if (t < NBMAX) g_hist[t] = 0;
    for (int i = t; i < out_elems; i += stride) out[i] = 0.0f;
}

// Peak detection: v > THRESH and no 7^3 in-bounds neighbor strictly greater.
// Equivalent to reference: thr = v*(v>THRESH); peak iff maxpool7(thr)==thr>0
// (neighbors <= THRESH have thr=0 < v, so raw-value comparison suffices).
__global__ void k_detect(const float* __restrict__ vol) {
    int t = blockIdx.x * blockDim.x + threadIdx.x;
    int i0 = t * 4;
    if (i0 >= NVOX) return;
    float4 q = *reinterpret_cast<const float4*>(vol + i0);
    float vv[4] = {q.x, q.y, q.z, q.w};
#pragma unroll
    for (int c = 0; c < 4; c++) {
        float v = vv[c];
        if (!(v > THRESH_F)) continue;
        int idx = i0 + c;
        int z = idx >> 18;
        int y = (idx >> 9) & (HH - 1);
        int x = idx & (WW - 1);
        int z0 = z - RAD < 0 ? 0 : z - RAD;
        int z1 = z + RAD >= DD ? DD - 1 : z + RAD;
        int y0 = y - RAD < 0 ? 0 : y - RAD;
        int y1 = y + RAD >= HH ? HH - 1 : y + RAD;
        int x0 = x - RAD < 0 ? 0 : x - RAD;
        int x1 = x + RAD >= WW ? WW - 1 : x + RAD;
        bool peak = true;
        // Cheap pre-check: candidate's own row segment (hot in L1 from the
        // streaming load) — rejects some candidates without touching other rows.
        {
            const float* row = vol + ((size_t)z << 18) + ((size_t)y << 9);
            for (int xx = x0; xx <= x1; xx++) {
                if (row[xx] > v) { peak = false; break; }
            }
        }
        // Full 7^3 scan (skipping the already-checked center row).
        for (int zz = z0; zz <= z1 && peak; zz++) {
            for (int yy = y0; yy <= y1 && peak; yy++) {
                if (zz == z && yy == y) continue;
                const float* row = vol + ((size_t)zz << 18) + ((size_t)yy << 9);
                for (int xx = x0; xx <= x1; xx++) {
                    if (row[xx] > v) { peak = false; break; }
                }
            }
        }
        if (peak) {
            int pos = atomicAdd(&g_count, 1);
            if (pos < CAP) {
                g_peak_idx[pos] = (unsigned)idx;
                g_peak_val[pos] = v;
                unsigned b = 0x3F800000u - __float_as_uint(v);  // bucket asc == value desc
                atomicAdd(&g_hist[b], 1);
            }
        }
    }
}

// Exclusive prefix scan over the 65536-bucket histogram. One block of 1024
// threads, 64 buckets per thread.
__global__ void k_scan() {
    __shared__ int sh[1024];
    int t = threadIdx.x;
    int base = t * 64;
    int s = 0;
#pragma unroll 8
    for (int j = 0; j < 64; j++) s += g_hist[base + j];
    sh[t] = s;
    __syncthreads();
    int own = s;
    for (int off = 1; off < 1024; off <<= 1) {
        int v = (t >= off) ? sh[t - off] : 0;
        __syncthreads();
        sh[t] += v;
        __syncthreads();
    }
    int run = sh[t] - own;  // exclusive prefix at chunk start
    for (int j = 0; j < 64; j++) {
        int c = g_hist[base + j];
        g_start[base + j] = run;
        g_cursor[base + j] = run;
        run += c;
    }
    if (t == 1023) g_start[NBMAX] = run;  // total peak count (<= CAP)
}

// Scatter peaks into their sorted bucket slots (order within bucket arbitrary;
// fixed up next — values inside a bucket are bit-identical).
__global__ void k_scatter() {
    int t = blockIdx.x * blockDim.x + threadIdx.x;
    int n = g_count < CAP ? g_count : CAP;
    if (t >= n) return;
    float v = g_peak_val[t];
    unsigned b = 0x3F800000u - __float_as_uint(v);
    int pos = atomicAdd(&g_cursor[b], 1);
    g_sorted_idx[pos] = g_peak_idx[t];
}

// Within each bucket (identical value), sort indices ascending to match
// lax.top_k's stable tie-break. Buckets have ~1-2 entries on average.
__global__ void k_bucketfix() {
    int b = blockIdx.x * blockDim.x + threadIdx.x;
    if (b >= NBMAX) return;
    int s = g_start[b];
    int e = g_start[b + 1];
    for (int i = s + 1; i < e; i++) {
        unsigned key = g_sorted_idx[i];
        int j = i - 1;
        while (j >= s && g_sorted_idx[j] > key) {
            g_sorted_idx[j + 1] = g_sorted_idx[j];
            j--;
        }
        g_sorted_idx[j + 1] = key;
    }
}

// One warp per output row: 7^3 weighted-centroid gather + affine transform.
// Out-of-bounds taps contribute zero (reference zero-pads the volume).
__global__ void k_centroid(const float* __restrict__ vol, float* __restrict__ out,
                           float* __restrict__ validf, unsigned char* __restrict__ validb) {
    int total = g_start[NBMAX];
    if (total > KP) total = KP;
    int gw = (blockIdx.x * blockDim.x + threadIdx.x) >> 5;
    int lane = threadIdx.x & 31;
    if (gw >= total) return;  // tail rows stay zero (pre-zeroed)

    unsigned idx = g_sorted_idx[gw];
    int z = idx >> 18;
    int y = (idx >> 9) & (HH - 1);
    int x = idx & (WW - 1);

    float s0 = 0.f, sx = 0.f, sy = 0.f, sz = 0.f;
#pragma unroll
    for (int p = lane; p < PATCH; p += 32) {
        int dz = p / 49;
        int r = p - dz * 49;
        int dy = r / 7;
        int dx = r - dy * 7;
        dz -= RAD; dy -= RAD; dx -= RAD;
        int zz = z + dz, yy = y + dy, xx = x + dx;
        if ((unsigned)zz < DD && (unsigned)yy < HH && (unsigned)xx < WW) {
            float w = vol[((size_t)zz << 18) + ((size_t)yy << 9) + xx];
            s0 += w;
            sx += w * (float)dx;
            sy += w * (float)dy;
            sz += w * (float)dz;
        }
    }
#pragma unroll
    for (int o = 16; o; o >>= 1) {
        s0 += __shfl_xor_sync(0xffffffffu, s0, o);
        sx += __shfl_xor_sync(0xffffffffu, sx, o);
        sy += __shfl_xor_sync(0xffffffffu, sy, o);
        sz += __shfl_xor_sync(0xffffffffu, sz, o);
    }
    if (lane == 0) {
        float val = vol[idx];
        float xr = ((float)x + sx / s0 - 255.5f) * 0.1f;          // (W-1)/2 = 255.5, PS_XY
        float yr = ((float)y + sy / s0 - 255.5f) * 0.1f;          // (H-1)/2 = 255.5, PS_XY
        float zr = ((float)z + sz / s0 + 0.5f) * 0.02f + (-2.0f); // PS_Z, ZMIN
        float4 row = make_float4(xr, yr, zr, val);
        *reinterpret_cast<float4*>(out + 4 * (size_t)gw) = row;
        if (validf) validf[gw] = 1.0f;
        if (validb) validb[gw] = 1;
    }
}

// ---------------- launch ----------------
extern "C" void kernel_launch(void* const* d_in, const int* in_sizes, int n_in,
                              void* d_out, int out_size) {
    const float* vol = (const float*)d_in[0];
    float* out = (float*)d_out;

    // Output layout: out[K,4] f32, then (maybe) valid[K] as f32 or u8.
    float* validf = nullptr;
    unsigned char* validb = nullptr;
    if (out_size >= 5 * KP) {
        validf = out + 4 * (size_t)KP;
    } else if (out_size >= 4 * KP + KP / 4) {
        validb = (unsigned char*)(out + 4 * (size_t)KP);
    }

    // 1. init: zero counter, histogram, and whole output buffer
    k_init<<<256, 256>>>(out, out_size);

    // 2. detect peaks (float4 streaming read of the whole volume)
    k_detect<<<(NVOX / 4 + 255) / 256, 256>>>(vol);

    // 3. exact counting sort by float bits (value desc), stable on index
    k_scan<<<1, 1024>>>();
    k_scatter<<<CAP / 256, 256>>>();
    k_bucketfix<<<NBMAX / 256, 256>>>();

    // 4. per-peak centroid + transform; one warp per output row
    k_centroid<<<(KP * 32) / 512, 512>>>(vol, out, validf, validb);
}

// round 15
// speedup vs baseline: 1.6593x; 1.6593x over previous
#include <cuda_runtime.h>
#include <cuda_bf16.h>

// Problem constants (fixed by the benchmark's setup_inputs)
#define DD 128
#define HH 512
#define WW 512
#define NVOX (DD * HH * WW)     // 33554432
#define RAD 3
#define PATCH 343               // 7*7*7
#define KP 131072               // max_peaks
#define CAP (1 << 18)           // peak record capacity (expected ~65k peaks)
#define CANDCAP (1 << 18)       // candidate capacity (expected ~100k)
#define NBMAX 65536             // bucket array size; actual max bucket ~50331
#define THRESH_F 0.997f
#define SLIST 1024              // per-block candidate staging (E~49, 100+ sigma margin)

// ---------------- device scratch (static; no allocations) ----------------
__device__ int g_ncand;
__device__ unsigned g_cand[CANDCAP];
__device__ int g_count;
__device__ int g_hist[NBMAX];
__device__ int g_start[NBMAX + 1];
__device__ int g_cursor[NBMAX];
__device__ unsigned g_peak_idx[CAP];
__device__ float g_peak_val[CAP];
__device__ float4 g_sums[CAP];       // s0, sx, sy, sz per peak
__device__ int g_sorted_rec[CAP];    // record ids in sorted output order

// ---------------- kernels ----------------

// Zero counters, histogram, and the output buffer (d_out is poisoned 0xAA).
__global__ void k_init(float* out, int out_elems) {
    int t = blockIdx.x * blockDim.x + threadIdx.x;
    int stride = gridDim.x * blockDim.x;
    if (t == 0) { g_count = 0; g_ncand = 0; }
    if (t < NBMAX) g_hist[t] = 0;
    for (int i = t; i < out_elems; i += stride) out[i] = 0.0f;
}

// Phase A: streaming threshold scan. Candidates staged in shared memory,
// flushed with ONE global atomic per block (~2k atomics total vs ~100k).
__global__ void k_cand(const float* __restrict__ vol) {
    __shared__ unsigned s_list[SLIST];
    __shared__ int s_n, s_base;
    if (threadIdx.x == 0) s_n = 0;
    __syncthreads();
    const int nquad = NVOX / 4;
    for (int q = blockIdx.x * blockDim.x + threadIdx.x; q < nquad;
         q += gridDim.x * blockDim.x) {
        float4 f = reinterpret_cast<const float4*>(vol)[q];
        int i0 = q * 4;
        if (f.x > THRESH_F) { int p = atomicAdd(&s_n, 1); if (p < SLIST) s_list[p] = i0; }
        if (f.y > THRESH_F) { int p = atomicAdd(&s_n, 1); if (p < SLIST) s_list[p] = i0 + 1; }
        if (f.z > THRESH_F) { int p = atomicAdd(&s_n, 1); if (p < SLIST) s_list[p] = i0 + 2; }
        if (f.w > THRESH_F) { int p = atomicAdd(&s_n, 1); if (p < SLIST) s_list[p] = i0 + 3; }
    }
    __syncthreads();
    int m = s_n < SLIST ? s_n : SLIST;
    if (threadIdx.x == 0) s_base = atomicAdd(&g_ncand, m);
    __syncthreads();
    for (int i = threadIdx.x; i < m; i += blockDim.x) {
        int dst = s_base + i;
        if (dst < CANDCAP) g_cand[dst] = s_list[i];
    }
}

// Phase B: one warp per candidate. Cooperative 7^3 window pass computes the
// window max (peak test) AND the centroid sums in one shot. Peak iff no
// in-bounds tap exceeds v (max includes center, so peak <=> !(max > v)) —
// identical semantics to reference maxpool(thr)==thr>0 with zero-pad.
__global__ void k_peakcheck(const float* __restrict__ vol) {
    int ncand = g_ncand; if (ncand > CANDCAP) ncand = CANDCAP;
    int nwarps = (gridDim.x * blockDim.x) >> 5;
    int gw0 = (blockIdx.x * blockDim.x + threadIdx.x) >> 5;
    int lane = threadIdx.x & 31;
    for (int c = gw0; c < ncand; c += nwarps) {
        unsigned idx = g_cand[c];
        int z = idx >> 18;
        int y = (idx >> 9) & (HH - 1);
        int x = idx & (WW - 1);
        float v = vol[idx];  // broadcast load (same addr all lanes)
        float mx = -1.0f, s0 = 0.f, sx = 0.f, sy = 0.f, sz = 0.f;
#pragma unroll
        for (int p = lane; p < PATCH; p += 32) {
            int dz = p / 49;
            int r = p - dz * 49;
            int dy = r / 7;
            int dx = r - dy * 7;
            dz -= RAD; dy -= RAD; dx -= RAD;
            int zz = z + dz, yy = y + dy, xx = x + dx;
            if ((unsigned)zz < DD && (unsigned)yy < HH && (unsigned)xx < WW) {
                float w = vol[((size_t)zz << 18) + ((size_t)yy << 9) + xx];
                mx = fmaxf(mx, w);
                s0 += w;
                sx += w * (float)dx;
                sy += w * (float)dy;
                sz += w * (float)dz;
            }
        }
#pragma unroll
        for (int o = 16; o; o >>= 1) {
            mx = fmaxf(mx, __shfl_xor_sync(0xffffffffu, mx, o));
            s0 += __shfl_xor_sync(0xffffffffu, s0, o);
            sx += __shfl_xor_sync(0xffffffffu, sx, o);
            sy += __shfl_xor_sync(0xffffffffu, sy, o);
            sz += __shfl_xor_sync(0xffffffffu, sz, o);
        }
        if (lane == 0 && !(mx > v)) {
            int pos = atomicAdd(&g_count, 1);
            if (pos < CAP) {
                g_peak_idx[pos] = idx;
                g_peak_val[pos] = v;
                g_sums[pos] = make_float4(s0, sx, sy, sz);
                unsigned b = 0x3F800000u - __float_as_uint(v);  // bucket asc == value desc
                atomicAdd(&g_hist[b], 1);
            }
        }
    }
}

// Exclusive prefix scan over the 65536-bucket histogram. One block of 1024
// threads, 64 buckets per thread (int4 loads for the sum pass).
__global__ void k_scan() {
    __shared__ int sh[1024];
    int t = threadIdx.x;
    int base = t * 64;
    int s = 0;
#pragma unroll
    for (int j = 0; j < 16; j++) {
        int4 q = reinterpret_cast<const int4*>(g_hist + base)[j];
        s += q.x + q.y + q.z + q.w;
    }
    sh[t] = s;
    __syncthreads();
    int own = s;
    for (int off = 1; off < 1024; off <<= 1) {
        int v = (t >= off) ? sh[t - off] : 0;
        __syncthreads();
        sh[t] += v;
        __syncthreads();
    }
    int run = sh[t] - own;  // exclusive prefix at chunk start
    for (int j = 0; j < 64; j++) {
        int c = g_hist[base + j];
        g_start[base + j] = run;
        g_cursor[base + j] = run;
        run += c;
    }
    if (t == 1023) g_start[NBMAX] = run;  // total peak count (<= CAP)
}

// Scatter peak records into their sorted bucket slots (order within bucket
// arbitrary; values inside a bucket are bit-identical — fixed up next).
__global__ void k_scatter() {
    int n = g_count < CAP ? g_count : CAP;
    int stride = gridDim.x * blockDim.x;
    for (int t = blockIdx.x * blockDim.x + threadIdx.x; t < n; t += stride) {
        float v = g_peak_val[t];
        unsigned b = 0x3F800000u - __float_as_uint(v);
        int pos = atomicAdd(&g_cursor[b], 1);
        g_sorted_rec[pos] = t;
    }
}

// Within each bucket (identical value), sort records by volume index
// ascending to match lax.top_k's stable tie-break. Buckets avg ~1-2 entries.
__global__ void k_bucketfix() {
    int stride = gridDim.x * blockDim.x;
    for (int b = blockIdx.x * blockDim.x + threadIdx.x; b < NBMAX; b += stride) {
        int s = g_start[b];
        int e = g_start[b + 1];
        for (int i = s + 1; i < e; i++) {
            int rec = g_sorted_rec[i];
            unsigned key = g_peak_idx[rec];
            int j = i - 1;
            while (j >= s && g_peak_idx[g_sorted_rec[j]] > key) {
                g_sorted_rec[j + 1] = g_sorted_rec[j];
                j--;
            }
            g_sorted_rec[j + 1] = rec;
        }
    }
}

// One thread per output row: gather record, affine transform, write.
__global__ void k_finalize(float* __restrict__ out, float* __restrict__ validf,
                           unsigned char* __restrict__ validb) {
    int total = g_start[NBMAX];
    if (total > KP) total = KP;
    int r = blockIdx.x * blockDim.x + threadIdx.x;
    if (r >= total) return;  // tail rows stay zero (pre-zeroed)
    int rec = g_sorted_rec[r];
    unsigned idx = g_peak_idx[rec];
    float val = g_peak_val[rec];
    float4 s = g_sums[rec];
    int z = idx >> 18;
    int y = (idx >> 9) & (HH - 1);
    int x = idx & (WW - 1);
    float xr = ((float)x + s.y / s.x - 255.5f) * 0.1f;            // (W-1)/2, PS_XY
    float yr = ((float)y + s.z / s.x - 255.5f) * 0.1f;            // (H-1)/2, PS_XY
    float zr = ((float)z + s.w / s.x + 0.5f) * 0.02f + (-2.0f);   // PS_Z, ZMIN
    *reinterpret_cast<float4*>(out + 4 * (size_t)r) = make_float4(xr, yr, zr, val);
    if (validf) validf[r] = 1.0f;
    if (validb) validb[r] = 1;
}

// ---------------- launch ----------------
extern "C" void kernel_launch(void* const* d_in, const int* in_sizes, int n_in,
                              void* d_out, int out_size) {
    const float* vol = (const float*)d_in[0];
    float* out = (float*)d_out;

    // Output layout: out[K,4] f32, then (maybe) valid[K] as f32 or u8.
    float* validf = nullptr;
    unsigned char* validb = nullptr;
    if (out_size >= 5 * KP) {
        validf = out + 4 * (size_t)KP;
    } else if (out_size >= 4 * KP + KP / 4) {
        validb = (unsigned char*)(out + 4 * (size_t)KP);
    }

    // 1. init: zero counters, histogram, whole output buffer
    k_init<<<256, 256>>>(out, out_size);

    // 2. Phase A: streaming threshold scan -> candidate list
    k_cand<<<2048, 256>>>(vol);

    // 3. Phase B: warp-per-candidate peak test + fused centroid sums
    k_peakcheck<<<2048, 512>>>(vol);

    // 4. exact counting sort by float bits (value desc), stable on index
    k_scan<<<1, 1024>>>();
    k_scatter<<<2048, 256>>>();
    k_bucketfix<<<256, 256>>>();

    // 5. per-row transform + write
    k_finalize<<<(KP + 255) / 256, 256>>>(out, validf, validb);
}